// round 7
// baseline (speedup 1.0000x reference)
#include <cuda_runtime.h>
#include <cuda_bf16.h>
#include <cstdint>

// Problem dims (fixed by the reference)
#define BATCH 4
#define SEQ   2048
#define DMODEL 1024
#define HEADS 16
#define DHEAD 64
#define ROWS  (BATCH * SEQ)   // 8192

// -------------------- scratch (device globals; no runtime alloc) ------------
__device__ float g_q[ROWS * DMODEL];
__device__ float g_k[ROWS * DMODEL];
__device__ float g_v[ROWS * DMODEL];
__device__ float g_attn[ROWS * DMODEL];

// -------------------- tf32 helpers ------------------------------------------
__device__ __forceinline__ uint32_t f2tf32(float x) {
    uint32_t y;
    asm volatile("cvt.rna.tf32.f32 %0, %1;" : "=r"(y) : "f"(x));
    return y;
}

__device__ __forceinline__ void mma_tf32(float c[4], const uint32_t a[4], const uint32_t b[2]) {
    asm volatile(
        "mma.sync.aligned.m16n8k8.row.col.f32.tf32.tf32.f32 "
        "{%0,%1,%2,%3}, {%4,%5,%6,%7}, {%8,%9}, {%0,%1,%2,%3};\n"
        : "+f"(c[0]), "+f"(c[1]), "+f"(c[2]), "+f"(c[3])
        : "r"(a[0]), "r"(a[1]), "r"(a[2]), "r"(a[3]),
          "r"(b[0]), "r"(b[1]));
}

// ============================================================================
// tf32 GEMM: C[M,N] = A[M,K] * B[K,N], all row-major fp32.
// Block tile 128x128, K-tile 32. 256 threads (8 warps).
// Warp grid: 4 (M, 32 rows each) x 2 (N, 64 cols each).
// ============================================================================
#define GBM 128
#define GBN 128
#define GBK 32

__global__ void __launch_bounds__(256)
gemm_tf32_kernel(const float* __restrict__ A, const float* __restrict__ B,
                 float* __restrict__ C, int M, int N, int K) {
    __shared__ uint32_t As[GBM][GBK + 4];    // stride 36: A-frag bank-free
    __shared__ uint32_t Bs[GBK][GBN + 8];    // stride 136: B-frag bank-free

    const int tid  = threadIdx.x;
    const int wid  = tid >> 5;
    const int lane = tid & 31;
    const int g    = lane >> 2;   // groupID (row within 8)
    const int tg   = lane & 3;    // thread-in-group (k / col pair)
    const int wm   = (wid & 3) * 32;
    const int wn   = (wid >> 2) * 64;
    const int bm   = blockIdx.y * GBM;
    const int bn   = blockIdx.x * GBN;

    float acc[2][8][4];
    #pragma unroll
    for (int mi = 0; mi < 2; mi++)
        #pragma unroll
        for (int ni = 0; ni < 8; ni++)
            #pragma unroll
            for (int j = 0; j < 4; j++) acc[mi][ni][j] = 0.0f;

    for (int k0 = 0; k0 < K; k0 += GBK) {
        // ---- load A tile 128x32 (1024 float4, 4 per thread), tf32-round ----
        #pragma unroll
        for (int i = 0; i < 4; i++) {
            int f  = tid + i * 256;
            int r  = f >> 3;
            int c4 = (f & 7) << 2;
            float4 v = *(const float4*)(A + (size_t)(bm + r) * K + k0 + c4);
            As[r][c4 + 0] = f2tf32(v.x);
            As[r][c4 + 1] = f2tf32(v.y);
            As[r][c4 + 2] = f2tf32(v.z);
            As[r][c4 + 3] = f2tf32(v.w);
        }
        // ---- load B tile 32x128 ----
        #pragma unroll
        for (int i = 0; i < 4; i++) {
            int f  = tid + i * 256;
            int r  = f >> 5;
            int c4 = (f & 31) << 2;
            float4 v = *(const float4*)(B + (size_t)(k0 + r) * N + bn + c4);
            Bs[r][c4 + 0] = f2tf32(v.x);
            Bs[r][c4 + 1] = f2tf32(v.y);
            Bs[r][c4 + 2] = f2tf32(v.z);
            Bs[r][c4 + 3] = f2tf32(v.w);
        }
        __syncthreads();

        #pragma unroll
        for (int kk = 0; kk < GBK; kk += 8) {
            uint32_t af[2][4];
            #pragma unroll
            for (int mi = 0; mi < 2; mi++) {
                int r = wm + mi * 16;
                af[mi][0] = As[r + g][kk + tg];
                af[mi][1] = As[r + g + 8][kk + tg];
                af[mi][2] = As[r + g][kk + tg + 4];
                af[mi][3] = As[r + g + 8][kk + tg + 4];
            }
            #pragma unroll
            for (int ni = 0; ni < 8; ni++) {
                uint32_t bf[2];
                bf[0] = Bs[kk + tg][wn + ni * 8 + g];
                bf[1] = Bs[kk + tg + 4][wn + ni * 8 + g];
                mma_tf32(acc[0][ni], af[0], bf);
                mma_tf32(acc[1][ni], af[1], bf);
            }
        }
        __syncthreads();
    }

    // ---- epilogue ----
    #pragma unroll
    for (int mi = 0; mi < 2; mi++) {
        #pragma unroll
        for (int ni = 0; ni < 8; ni++) {
            int row = bm + wm + mi * 16 + g;
            int col = bn + wn + ni * 8 + 2 * tg;
            float2 v01 = make_float2(acc[mi][ni][0], acc[mi][ni][1]);
            float2 v23 = make_float2(acc[mi][ni][2], acc[mi][ni][3]);
            *(float2*)(C + (size_t)row * N + col)       = v01;
            *(float2*)(C + (size_t)(row + 8) * N + col) = v23;
        }
    }
}

// ============================================================================
// Flash attention (tf32 mma): one block per (q-tile of 64, batch*head).
// 128 threads = 4 warps; each warp owns 16 query rows. Online softmax.
// Smem (dynamic, ~69 KB): Qs[64][68], Ks[64][68], Vs[64][72], Ps[4][16][68]
// ============================================================================
#define FQ_STRIDE 68
#define FK_STRIDE 68
#define FV_STRIDE 72
#define FP_STRIDE 68
#define FLASH_SMEM_WORDS (64 * FQ_STRIDE + 64 * FK_STRIDE + 64 * FV_STRIDE + 4 * 16 * FP_STRIDE)
#define FLASH_SMEM_BYTES (FLASH_SMEM_WORDS * 4)

__global__ void __launch_bounds__(128)
flash_kernel(const float* __restrict__ Q, const float* __restrict__ Kb,
             const float* __restrict__ Vb, float* __restrict__ O) {
    extern __shared__ uint32_t sm[];
    uint32_t* Qs = sm;                          // 64 x 68
    uint32_t* Ks = Qs + 64 * FQ_STRIDE;         // 64 x 68
    uint32_t* Vs = Ks + 64 * FK_STRIDE;         // 64 x 72
    uint32_t* Ps = Vs + 64 * FV_STRIDE;         // 4 x 16 x 68

    const int tid  = threadIdx.x;
    const int wid  = tid >> 5;
    const int lane = tid & 31;
    const int g    = lane >> 2;
    const int tg   = lane & 3;

    const int bh = blockIdx.y;
    const int b  = bh >> 4;          // / HEADS
    const int hh = bh & 15;          // % HEADS
    const int q0 = blockIdx.x * 64;

    const float scale = 0.125f;      // 1/sqrt(64)

    // ---- load Q tile (scaled, tf32-rounded) ----
    const float* qbase = Q + ((size_t)(b * SEQ + q0)) * DMODEL + hh * DHEAD;
    #pragma unroll
    for (int i = 0; i < 8; i++) {
        int f  = tid + i * 128;
        int r  = f >> 4;
        int c4 = (f & 15) << 2;
        float4 v = *(const float4*)(qbase + (size_t)r * DMODEL + c4);
        Qs[r * FQ_STRIDE + c4 + 0] = f2tf32(v.x * scale);
        Qs[r * FQ_STRIDE + c4 + 1] = f2tf32(v.y * scale);
        Qs[r * FQ_STRIDE + c4 + 2] = f2tf32(v.z * scale);
        Qs[r * FQ_STRIDE + c4 + 3] = f2tf32(v.w * scale);
    }
    __syncthreads();

    // ---- Q A-fragments for all 8 k-steps (d=64) ----
    uint32_t qa[8][4];
    {
        int r = wid * 16 + g;
        #pragma unroll
        for (int kk = 0; kk < 8; kk++) {
            qa[kk][0] = Qs[r * FQ_STRIDE + kk * 8 + tg];
            qa[kk][1] = Qs[(r + 8) * FQ_STRIDE + kk * 8 + tg];
            qa[kk][2] = Qs[r * FQ_STRIDE + kk * 8 + tg + 4];
            qa[kk][3] = Qs[(r + 8) * FQ_STRIDE + kk * 8 + tg + 4];
        }
    }

    float o[8][4];
    #pragma unroll
    for (int di = 0; di < 8; di++)
        #pragma unroll
        for (int j = 0; j < 4; j++) o[di][j] = 0.0f;
    float mrow0 = -1e30f, mrow1 = -1e30f;
    float lrow0 = 0.0f,  lrow1 = 0.0f;

    const float* kbase = Kb + (size_t)b * SEQ * DMODEL + hh * DHEAD;
    const float* vbase = Vb + (size_t)b * SEQ * DMODEL + hh * DHEAD;
    uint32_t* Pw = Ps + wid * 16 * FP_STRIDE;

    for (int n0 = 0; n0 < SEQ; n0 += 64) {
        __syncthreads();   // previous tile's smem reads are done
        // ---- load K,V tiles (tf32-rounded at store) ----
        #pragma unroll
        for (int i = 0; i < 8; i++) {
            int f  = tid + i * 128;
            int r  = f >> 4;
            int c4 = (f & 15) << 2;
            float4 kv = *(const float4*)(kbase + (size_t)(n0 + r) * DMODEL + c4);
            Ks[r * FK_STRIDE + c4 + 0] = f2tf32(kv.x);
            Ks[r * FK_STRIDE + c4 + 1] = f2tf32(kv.y);
            Ks[r * FK_STRIDE + c4 + 2] = f2tf32(kv.z);
            Ks[r * FK_STRIDE + c4 + 3] = f2tf32(kv.w);
            float4 vv = *(const float4*)(vbase + (size_t)(n0 + r) * DMODEL + c4);
            Vs[r * FV_STRIDE + c4 + 0] = f2tf32(vv.x);
            Vs[r * FV_STRIDE + c4 + 1] = f2tf32(vv.y);
            Vs[r * FV_STRIDE + c4 + 2] = f2tf32(vv.z);
            Vs[r * FV_STRIDE + c4 + 3] = f2tf32(vv.w);
        }
        __syncthreads();

        // ---- S = (Q*scale) K^T : 16 rows x 64 keys per warp ----
        float s[8][4];
        #pragma unroll
        for (int ni = 0; ni < 8; ni++)
            #pragma unroll
            for (int j = 0; j < 4; j++) s[ni][j] = 0.0f;

        #pragma unroll
        for (int ni = 0; ni < 8; ni++) {
            #pragma unroll
            for (int kk = 0; kk < 8; kk++) {
                uint32_t bf[2];
                bf[0] = Ks[(ni * 8 + g) * FK_STRIDE + kk * 8 + tg];
                bf[1] = Ks[(ni * 8 + g) * FK_STRIDE + kk * 8 + tg + 4];
                mma_tf32(s[ni], qa[kk], bf);
            }
        }

        // ---- online softmax (each thread owns 2 rows: g and g+8) ----
        float tmax0 = -1e30f, tmax1 = -1e30f;
        #pragma unroll
        for (int ni = 0; ni < 8; ni++) {
            tmax0 = fmaxf(tmax0, fmaxf(s[ni][0], s[ni][1]));
            tmax1 = fmaxf(tmax1, fmaxf(s[ni][2], s[ni][3]));
        }
        tmax0 = fmaxf(tmax0, __shfl_xor_sync(0xffffffffu, tmax0, 1));
        tmax0 = fmaxf(tmax0, __shfl_xor_sync(0xffffffffu, tmax0, 2));
        tmax1 = fmaxf(tmax1, __shfl_xor_sync(0xffffffffu, tmax1, 1));
        tmax1 = fmaxf(tmax1, __shfl_xor_sync(0xffffffffu, tmax1, 2));

        float mnew0 = fmaxf(mrow0, tmax0);
        float mnew1 = fmaxf(mrow1, tmax1);
        float alpha0 = __expf(mrow0 - mnew0);
        float alpha1 = __expf(mrow1 - mnew1);

        float rs0 = 0.0f, rs1 = 0.0f;
        #pragma unroll
        for (int ni = 0; ni < 8; ni++) {
            float p0 = __expf(s[ni][0] - mnew0);
            float p1 = __expf(s[ni][1] - mnew0);
            float p2 = __expf(s[ni][2] - mnew1);
            float p3 = __expf(s[ni][3] - mnew1);
            rs0 += p0 + p1;
            rs1 += p2 + p3;
            Pw[g * FP_STRIDE + ni * 8 + 2 * tg]           = f2tf32(p0);
            Pw[g * FP_STRIDE + ni * 8 + 2 * tg + 1]       = f2tf32(p1);
            Pw[(g + 8) * FP_STRIDE + ni * 8 + 2 * tg]     = f2tf32(p2);
            Pw[(g + 8) * FP_STRIDE + ni * 8 + 2 * tg + 1] = f2tf32(p3);
        }
        rs0 += __shfl_xor_sync(0xffffffffu, rs0, 1);
        rs0 += __shfl_xor_sync(0xffffffffu, rs0, 2);
        rs1 += __shfl_xor_sync(0xffffffffu, rs1, 1);
        rs1 += __shfl_xor_sync(0xffffffffu, rs1, 2);

        mrow0 = mnew0; mrow1 = mnew1;
        lrow0 = lrow0 * alpha0 + rs0;
        lrow1 = lrow1 * alpha1 + rs1;

        #pragma unroll
        for (int di = 0; di < 8; di++) {
            o[di][0] *= alpha0;
            o[di][1] *= alpha0;
            o[di][2] *= alpha1;
            o[di][3] *= alpha1;
        }
        __syncwarp();   // order P stores before P A-fragment loads (same warp)

        // ---- O += P V ----
        #pragma unroll
        for (int kk = 0; kk < 8; kk++) {
            uint32_t af[4];
            af[0] = Pw[g * FP_STRIDE + kk * 8 + tg];
            af[1] = Pw[(g + 8) * FP_STRIDE + kk * 8 + tg];
            af[2] = Pw[g * FP_STRIDE + kk * 8 + tg + 4];
            af[3] = Pw[(g + 8) * FP_STRIDE + kk * 8 + tg + 4];
            #pragma unroll
            for (int di = 0; di < 8; di++) {
                uint32_t bf[2];
                bf[0] = Vs[(kk * 8 + tg) * FV_STRIDE + di * 8 + g];
                bf[1] = Vs[(kk * 8 + tg + 4) * FV_STRIDE + di * 8 + g];
                mma_tf32(o[di], af, bf);
            }
        }
    }

    // ---- normalize and write ----
    float inv0 = 1.0f / lrow0;
    float inv1 = 1.0f / lrow1;
    int row0 = q0 + wid * 16 + g;
    int row1 = row0 + 8;
    #pragma unroll
    for (int di = 0; di < 8; di++) {
        int col = hh * DHEAD + di * 8 + 2 * tg;
        float2 v01 = make_float2(o[di][0] * inv0, o[di][1] * inv0);
        float2 v23 = make_float2(o[di][2] * inv1, o[di][3] * inv1);
        *(float2*)(O + (size_t)(b * SEQ + row0) * DMODEL + col) = v01;
        *(float2*)(O + (size_t)(b * SEQ + row1) * DMODEL + col) = v23;
    }
}

// ============================================================================
// kernel_launch
// ============================================================================
extern "C" void kernel_launch(void* const* d_in, const int* in_sizes, int n_in,
                              void* d_out, int out_size) {
    (void)in_sizes; (void)n_in; (void)out_size;
    const float* x  = (const float*)d_in[0];
    const float* Wq = (const float*)d_in[1];
    const float* Wk = (const float*)d_in[2];
    const float* Wv = (const float*)d_in[3];
    const float* Wo = (const float*)d_in[4];
    float* out = (float*)d_out;

    float *q, *k, *v, *attn;
    cudaGetSymbolAddress((void**)&q,    g_q);
    cudaGetSymbolAddress((void**)&k,    g_k);
    cudaGetSymbolAddress((void**)&v,    g_v);
    cudaGetSymbolAddress((void**)&attn, g_attn);

    dim3 ggrid(DMODEL / GBN, ROWS / GBM);   // (8, 64)

    gemm_tf32_kernel<<<ggrid, 256>>>(x, Wq, q, ROWS, DMODEL, DMODEL);
    gemm_tf32_kernel<<<ggrid, 256>>>(x, Wk, k, ROWS, DMODEL, DMODEL);
    gemm_tf32_kernel<<<ggrid, 256>>>(x, Wv, v, ROWS, DMODEL, DMODEL);

    cudaFuncSetAttribute(flash_kernel,
                         cudaFuncAttributeMaxDynamicSharedMemorySize,
                         FLASH_SMEM_BYTES);
    flash_kernel<<<dim3(SEQ / 64, BATCH * HEADS), 128, FLASH_SMEM_BYTES>>>(q, k, v, attn);

    gemm_tf32_kernel<<<ggrid, 256>>>(attn, Wo, out, ROWS, DMODEL, DMODEL);
}